// round 2
// baseline (speedup 1.0000x reference)
#include <cuda_runtime.h>
#include <math.h>
#include <stdint.h>

#define Bb 128
#define Tt 576
#define Dd 1024
#define Hh 1024
#define Uu 512
#define Mm (Bb*Tt)   // 73728

// ---------------- scratch (device globals; no allocs allowed) ----------------
__device__ float g_projh[Bb*Uu];
__device__ float g_score[Mm];
__device__ float g_weights[Mm];

// ---------------- helpers ----------------
__device__ __forceinline__ float tf32r(float x){
    uint32_t u;
    asm("cvt.rna.tf32.f32 %0, %1;" : "=r"(u) : "f"(x));
    return __uint_as_float(u);
}

__device__ __forceinline__ void mma_tf32(float* c, const uint32_t* a, const uint32_t* b){
    asm volatile(
        "mma.sync.aligned.m16n8k8.row.col.f32.tf32.tf32.f32 "
        "{%0,%1,%2,%3}, {%4,%5,%6,%7}, {%8,%9}, {%0,%1,%2,%3};"
        : "+f"(c[0]), "+f"(c[1]), "+f"(c[2]), "+f"(c[3])
        : "r"(a[0]), "r"(a[1]), "r"(a[2]), "r"(a[3]),
          "r"(b[0]), "r"(b[1]));
}

// ---------------- kernel 0: zero the score accumulator ----------------
__global__ void zero_score_kernel(){
    int i = blockIdx.x * blockDim.x + threadIdx.x;
    if (i < Mm) g_score[i] = 0.0f;
}

// ---------------- kernel 1: proj_h = hidden @ W2 + W2_b ----------------
__global__ void projh_kernel(const float* __restrict__ hidden,
                             const float* __restrict__ W2,
                             const float* __restrict__ W2b){
    __shared__ float sh[Hh];
    const int b = blockIdx.x;
    const int u = threadIdx.x;            // 512 threads
    for (int h = threadIdx.x; h < Hh; h += blockDim.x) sh[h] = hidden[b*Hh + h];
    __syncthreads();
    float acc = W2b[u];
    #pragma unroll 8
    for (int h = 0; h < Hh; ++h) acc += sh[h] * W2[h*Uu + u];
    g_projh[b*Uu + u] = acc;
}

// ---------------- kernel 2: fused GEMM + tanh + V contraction ----------------
// score[m] += sum_n tanh( (A@W1)[m,n] + W1b[n] + projh[b(m),n] ) * Vw[n]
#define BM 128
#define BN 128
#define BK 32
#define SA_STRIDE 36     // BK + 4  -> conflict-free A-frag loads, 16B aligned
#define SB_STRIDE 136    // BN + 8  -> conflict-free B-frag loads, 16B aligned
#define GEMM_SMEM_BYTES (2*(BM*SA_STRIDE + BK*SB_STRIDE)*4)   // 71680

extern __shared__ float smem_dyn[];

__global__ void __launch_bounds__(256, 1)
gemm_score_kernel(const float* __restrict__ A,    // features [Mm, Dd]
                  const float* __restrict__ W1,   // [Dd, Uu]
                  const float* __restrict__ W1b,  // [Uu]
                  const float* __restrict__ Vw)   // [Uu]
{
    float* sA = smem_dyn;                          // [2][BM][SA_STRIDE]
    float* sB = smem_dyn + 2*BM*SA_STRIDE;         // [2][BK][SB_STRIDE]

    const int tid    = threadIdx.x;
    const int lane   = tid & 31;
    const int w      = tid >> 5;        // 8 warps
    const int warp_m = w >> 1;          // 0..3  (32 rows each)
    const int warp_n = w & 1;           // 0..1  (64 cols each)
    const int gid    = lane >> 2;
    const int tg     = lane & 3;
    const int m0     = blockIdx.y * BM; // gridDim.y = 576
    const int n0     = blockIdx.x * BN; // gridDim.x = 4 (consecutive bids share A tile -> L2 reuse)

    float4 pa[4], pb[4];
    float acc[2][8][4];
    #pragma unroll
    for (int i=0;i<2;i++)
        #pragma unroll
        for (int j=0;j<8;j++)
            #pragma unroll
            for (int k=0;k<4;k++) acc[i][j][k] = 0.0f;

    auto loadA = [&](int kt){
        #pragma unroll
        for (int i=0;i<4;i++){
            int s = tid + i*256;            // 1024 float4 slots
            int row = s >> 3, kk = (s & 7) * 4;
            pa[i] = *reinterpret_cast<const float4*>(&A[(size_t)(m0+row)*Dd + kt*BK + kk]);
        }
    };
    auto loadB = [&](int kt){
        #pragma unroll
        for (int i=0;i<4;i++){
            int s = tid + i*256;
            int krow = s >> 5, nn = (s & 31) * 4;
            pb[i] = *reinterpret_cast<const float4*>(&W1[(size_t)(kt*BK+krow)*Uu + n0 + nn]);
        }
    };
    auto storeAB = [&](int buf){
        float* dA = sA + buf*BM*SA_STRIDE;
        float* dB = sB + buf*BK*SB_STRIDE;
        #pragma unroll
        for (int i=0;i<4;i++){
            int s = tid + i*256;
            int row = s >> 3, kk = (s & 7) * 4;
            float4 v = pa[i];
            v.x = tf32r(v.x); v.y = tf32r(v.y); v.z = tf32r(v.z); v.w = tf32r(v.w);
            *reinterpret_cast<float4*>(&dA[row*SA_STRIDE + kk]) = v;
        }
        #pragma unroll
        for (int i=0;i<4;i++){
            int s = tid + i*256;
            int krow = s >> 5, nn = (s & 31) * 4;
            float4 v = pb[i];
            v.x = tf32r(v.x); v.y = tf32r(v.y); v.z = tf32r(v.z); v.w = tf32r(v.w);
            *reinterpret_cast<float4*>(&dB[krow*SB_STRIDE + nn]) = v;
        }
    };
    auto compute = [&](int buf){
        const float* cA = sA + buf*BM*SA_STRIDE;
        const float* cB = sB + buf*BK*SB_STRIDE;
        #pragma unroll
        for (int ks=0; ks<4; ks++){
            const int k8 = ks*8;
            uint32_t af[2][4], bf[8][2];
            #pragma unroll
            for (int mi=0;mi<2;mi++){
                int r = warp_m*32 + mi*16 + gid;
                af[mi][0] = __float_as_uint(cA[(r  )*SA_STRIDE + k8 + tg    ]);
                af[mi][1] = __float_as_uint(cA[(r+8)*SA_STRIDE + k8 + tg    ]);
                af[mi][2] = __float_as_uint(cA[(r  )*SA_STRIDE + k8 + tg + 4]);
                af[mi][3] = __float_as_uint(cA[(r+8)*SA_STRIDE + k8 + tg + 4]);
            }
            #pragma unroll
            for (int ni=0;ni<8;ni++){
                int cc = warp_n*64 + ni*8 + gid;
                bf[ni][0] = __float_as_uint(cB[(k8 + tg    )*SB_STRIDE + cc]);
                bf[ni][1] = __float_as_uint(cB[(k8 + tg + 4)*SB_STRIDE + cc]);
            }
            #pragma unroll
            for (int mi=0;mi<2;mi++)
                #pragma unroll
                for (int ni=0;ni<8;ni++)
                    mma_tf32(acc[mi][ni], af[mi], bf[ni]);
        }
    };

    loadA(0); loadB(0);
    storeAB(0);
    __syncthreads();

    const int NKT = Dd / BK;   // 32
    for (int kt = 0; kt < NKT; ++kt){
        const int cur = kt & 1;
        if (kt + 1 < NKT){ loadA(kt+1); loadB(kt+1); }
        compute(cur);
        if (kt + 1 < NKT){
            storeAB(cur ^ 1);
            __syncthreads();
        }
    }

    // ----- epilogue: tanh + V contraction, row-reduce, atomic accumulate -----
    const int col_base = n0 + warp_n*64;
    #pragma unroll
    for (int mi=0; mi<2; mi++){
        #pragma unroll
        for (int h=0; h<2; h++){
            const int row = m0 + warp_m*32 + mi*16 + 8*h + gid;
            const int b   = row / Tt;
            const float* ph = &g_projh[b*Uu];
            float rsum = 0.0f;
            #pragma unroll
            for (int ni=0; ni<8; ni++){
                const int c0 = col_base + ni*8 + tg*2;
                float v0 = acc[mi][ni][2*h + 0] + W1b[c0]     + ph[c0];
                float v1 = acc[mi][ni][2*h + 1] + W1b[c0 + 1] + ph[c0 + 1];
                rsum += tanhf(v0) * Vw[c0] + tanhf(v1) * Vw[c0 + 1];
            }
            rsum += __shfl_xor_sync(0xffffffffu, rsum, 1);
            rsum += __shfl_xor_sync(0xffffffffu, rsum, 2);
            if (tg == 0) atomicAdd(&g_score[row], rsum);
        }
    }
}

// ---------------- kernel 3: softmax over T per batch ----------------
__global__ void softmax_kernel(float* __restrict__ w_out){   // w_out may be null
    const int b    = blockIdx.x;
    const int tid  = threadIdx.x;       // 576 threads = 18 full warps
    const int lane = tid & 31;
    const int wid  = tid >> 5;
    __shared__ float sred[32];

    const float s = g_score[b*Tt + tid];

    // max reduce
    float v = s;
    #pragma unroll
    for (int o=16;o>0;o>>=1) v = fmaxf(v, __shfl_xor_sync(0xffffffffu, v, o));
    if (lane == 0) sred[wid] = v;
    __syncthreads();
    if (tid < 32){
        float m = (tid < 18) ? sred[tid] : -3.4e38f;
        #pragma unroll
        for (int o=16;o>0;o>>=1) m = fmaxf(m, __shfl_xor_sync(0xffffffffu, m, o));
        sred[tid] = m;
    }
    __syncthreads();
    const float mx = sred[0];
    const float e  = expf(s - mx);
    __syncthreads();     // done reading sred before reuse

    // sum reduce
    float t = e;
    #pragma unroll
    for (int o=16;o>0;o>>=1) t += __shfl_xor_sync(0xffffffffu, t, o);
    if (lane == 0) sred[wid] = t;
    __syncthreads();
    if (tid < 32){
        float su = (tid < 18) ? sred[tid] : 0.0f;
        #pragma unroll
        for (int o=16;o>0;o>>=1) su += __shfl_xor_sync(0xffffffffu, su, o);
        sred[tid] = su;
    }
    __syncthreads();
    const float total = sred[0];

    const float wgt = e / total;
    g_weights[b*Tt + tid] = wgt;
    if (w_out) w_out[b*Tt + tid] = wgt;
}

// ---------------- kernel 4: context = sum_t w[b,t] * features[b,t,:] ----------------
__global__ void context_kernel(const float* __restrict__ feat,
                               float* __restrict__ ctx){
    const int b = blockIdx.y;
    const int d = blockIdx.x * blockDim.x + threadIdx.x;   // blockDim 256, gridDim.x 4
    __shared__ float sw[Tt];
    for (int t = threadIdx.x; t < Tt; t += blockDim.x) sw[t] = g_weights[b*Tt + t];
    __syncthreads();
    const float* fb = feat + (size_t)b*Tt*Dd + d;
    float acc = 0.0f;
    #pragma unroll 4
    for (int t = 0; t < Tt; ++t) acc += sw[t] * fb[(size_t)t*Dd];
    ctx[b*Dd + d] = acc;
}

// ---------------- launch ----------------
extern "C" void kernel_launch(void* const* d_in, const int* in_sizes, int n_in,
                              void* d_out, int out_size){
    const float* features = (const float*)d_in[0];
    const float* hidden   = (const float*)d_in[1];
    const float* W1w      = (const float*)d_in[2];
    const float* W1b      = (const float*)d_in[3];
    const float* W2w      = (const float*)d_in[4];
    const float* W2b      = (const float*)d_in[5];
    const float* Vw       = (const float*)d_in[6];
    // d_in[7] = V_b: softmax is shift-invariant, so it cannot affect either output.

    float* out = (float*)d_out;
    float* ctx_out = nullptr;
    float* w_out   = nullptr;
    if (out_size >= Bb*Dd + Mm)      { ctx_out = out; w_out = out + Bb*Dd; }
    else if (out_size == Bb*Dd)      { ctx_out = out; }
    else if (out_size == Mm)         { w_out = out; }
    else                             { ctx_out = out; }

    cudaFuncSetAttribute(gemm_score_kernel,
                         cudaFuncAttributeMaxDynamicSharedMemorySize,
                         GEMM_SMEM_BYTES);

    zero_score_kernel<<<Mm/256, 256>>>();
    projh_kernel<<<Bb, Uu>>>(hidden, W2w, W2b);

    dim3 gg(Uu/BN, Mm/BM);   // (4, 576)
    gemm_score_kernel<<<gg, 256, GEMM_SMEM_BYTES>>>(features, W1w, W1b, Vw);

    softmax_kernel<<<Bb, Tt>>>(w_out);

    if (ctx_out){
        dim3 gc(Dd/256, Bb); // (4, 128)
        context_kernel<<<gc, 256>>>(features, ctx_out);
    }
}

// round 3
// speedup vs baseline: 1.0006x; 1.0006x over previous
#include <cuda_runtime.h>
#include <math.h>
#include <stdint.h>

#define Bb 128
#define Tt 576
#define Dd 1024
#define Hh 1024
#define Uu 512
#define Mm (Bb*Tt)   // 73728

// ---------------- scratch (device globals; no allocs allowed) ----------------
__device__ float g_projh[Bb*Uu];
__device__ float g_score[Mm];
__device__ float g_weights[Mm];

// ---------------- helpers ----------------
__device__ __forceinline__ float tf32r(float x){
    uint32_t u;
    asm("cvt.rna.tf32.f32 %0, %1;" : "=r"(u) : "f"(x));
    return __uint_as_float(u);
}

__device__ __forceinline__ void mma_tf32(float* c, const uint32_t* a, const uint32_t* b){
    asm volatile(
        "mma.sync.aligned.m16n8k8.row.col.f32.tf32.tf32.f32 "
        "{%0,%1,%2,%3}, {%4,%5,%6,%7}, {%8,%9}, {%0,%1,%2,%3};"
        : "+f"(c[0]), "+f"(c[1]), "+f"(c[2]), "+f"(c[3])
        : "r"(a[0]), "r"(a[1]), "r"(a[2]), "r"(a[3]),
          "r"(b[0]), "r"(b[1]));
}

// ---------------- kernel 0: zero the score accumulator ----------------
__global__ void zero_score_kernel(){
    int i = blockIdx.x * blockDim.x + threadIdx.x;
    if (i < Mm) g_score[i] = 0.0f;
}

// ---------------- kernel 1: proj_h = hidden @ W2 + W2_b ----------------
__global__ void projh_kernel(const float* __restrict__ hidden,
                             const float* __restrict__ W2,
                             const float* __restrict__ W2b){
    __shared__ float sh[Hh];
    const int b = blockIdx.x;
    const int u = threadIdx.x;            // 512 threads
    for (int h = threadIdx.x; h < Hh; h += blockDim.x) sh[h] = hidden[b*Hh + h];
    __syncthreads();
    float acc = W2b[u];
    #pragma unroll 8
    for (int h = 0; h < Hh; ++h) acc += sh[h] * W2[h*Uu + u];
    g_projh[b*Uu + u] = acc;
}

// ---------------- kernel 2: fused GEMM + tanh + V contraction ----------------
// score[m] += sum_n tanh( (A@W1)[m,n] + W1b[n] + projh[b(m),n] ) * Vw[n]
#define BM 128
#define BN 128
#define BK 32
#define SA_STRIDE 36     // BK + 4  -> conflict-free A-frag loads, 16B aligned
#define SB_STRIDE 136    // BN + 8  -> conflict-free B-frag loads, 16B aligned
#define GEMM_SMEM_BYTES (2*(BM*SA_STRIDE + BK*SB_STRIDE)*4)   // 71680

extern __shared__ float smem_dyn[];

__global__ void __launch_bounds__(256, 1)
gemm_score_kernel(const float* __restrict__ A,    // features [Mm, Dd]
                  const float* __restrict__ W1,   // [Dd, Uu]
                  const float* __restrict__ W1b,  // [Uu]
                  const float* __restrict__ Vw)   // [Uu]
{
    float* sA = smem_dyn;                          // [2][BM][SA_STRIDE]
    float* sB = smem_dyn + 2*BM*SA_STRIDE;         // [2][BK][SB_STRIDE]

    const int tid    = threadIdx.x;
    const int lane   = tid & 31;
    const int w      = tid >> 5;        // 8 warps
    const int warp_m = w >> 1;          // 0..3  (32 rows each)
    const int warp_n = w & 1;           // 0..1  (64 cols each)
    const int gid    = lane >> 2;
    const int tg     = lane & 3;
    const int m0     = blockIdx.y * BM; // gridDim.y = 576
    const int n0     = blockIdx.x * BN; // gridDim.x = 4 (consecutive bids share A tile -> L2 reuse)

    float4 pa[4], pb[4];
    float acc[2][8][4];
    #pragma unroll
    for (int i=0;i<2;i++)
        #pragma unroll
        for (int j=0;j<8;j++)
            #pragma unroll
            for (int k=0;k<4;k++) acc[i][j][k] = 0.0f;

    auto loadA = [&](int kt){
        #pragma unroll
        for (int i=0;i<4;i++){
            int s = tid + i*256;            // 1024 float4 slots
            int row = s >> 3, kk = (s & 7) * 4;
            pa[i] = *reinterpret_cast<const float4*>(&A[(size_t)(m0+row)*Dd + kt*BK + kk]);
        }
    };
    auto loadB = [&](int kt){
        #pragma unroll
        for (int i=0;i<4;i++){
            int s = tid + i*256;
            int krow = s >> 5, nn = (s & 31) * 4;
            pb[i] = *reinterpret_cast<const float4*>(&W1[(size_t)(kt*BK+krow)*Uu + n0 + nn]);
        }
    };
    auto storeAB = [&](int buf){
        float* dA = sA + buf*BM*SA_STRIDE;
        float* dB = sB + buf*BK*SB_STRIDE;
        #pragma unroll
        for (int i=0;i<4;i++){
            int s = tid + i*256;
            int row = s >> 3, kk = (s & 7) * 4;
            float4 v = pa[i];
            v.x = tf32r(v.x); v.y = tf32r(v.y); v.z = tf32r(v.z); v.w = tf32r(v.w);
            *reinterpret_cast<float4*>(&dA[row*SA_STRIDE + kk]) = v;
        }
        #pragma unroll
        for (int i=0;i<4;i++){
            int s = tid + i*256;
            int krow = s >> 5, nn = (s & 31) * 4;
            float4 v = pb[i];
            v.x = tf32r(v.x); v.y = tf32r(v.y); v.z = tf32r(v.z); v.w = tf32r(v.w);
            *reinterpret_cast<float4*>(&dB[krow*SB_STRIDE + nn]) = v;
        }
    };
    auto compute = [&](int buf){
        const float* cA = sA + buf*BM*SA_STRIDE;
        const float* cB = sB + buf*BK*SB_STRIDE;
        #pragma unroll
        for (int ks=0; ks<4; ks++){
            const int k8 = ks*8;
            uint32_t af[2][4], bf[8][2];
            #pragma unroll
            for (int mi=0;mi<2;mi++){
                int r = warp_m*32 + mi*16 + gid;
                af[mi][0] = __float_as_uint(cA[(r  )*SA_STRIDE + k8 + tg    ]);
                af[mi][1] = __float_as_uint(cA[(r+8)*SA_STRIDE + k8 + tg    ]);
                af[mi][2] = __float_as_uint(cA[(r  )*SA_STRIDE + k8 + tg + 4]);
                af[mi][3] = __float_as_uint(cA[(r+8)*SA_STRIDE + k8 + tg + 4]);
            }
            #pragma unroll
            for (int ni=0;ni<8;ni++){
                int cc = warp_n*64 + ni*8 + gid;
                bf[ni][0] = __float_as_uint(cB[(k8 + tg    )*SB_STRIDE + cc]);
                bf[ni][1] = __float_as_uint(cB[(k8 + tg + 4)*SB_STRIDE + cc]);
            }
            #pragma unroll
            for (int mi=0;mi<2;mi++)
                #pragma unroll
                for (int ni=0;ni<8;ni++)
                    mma_tf32(acc[mi][ni], af[mi], bf[ni]);
        }
    };

    loadA(0); loadB(0);
    storeAB(0);
    __syncthreads();

    const int NKT = Dd / BK;   // 32
    for (int kt = 0; kt < NKT; ++kt){
        const int cur = kt & 1;
        if (kt + 1 < NKT){ loadA(kt+1); loadB(kt+1); }
        compute(cur);
        if (kt + 1 < NKT){
            storeAB(cur ^ 1);
            __syncthreads();
        }
    }

    // ----- epilogue: tanh + V contraction, row-reduce, atomic accumulate -----
    const int col_base = n0 + warp_n*64;
    #pragma unroll
    for (int mi=0; mi<2; mi++){
        #pragma unroll
        for (int h=0; h<2; h++){
            const int row = m0 + warp_m*32 + mi*16 + 8*h + gid;
            const int b   = row / Tt;
            const float* ph = &g_projh[b*Uu];
            float rsum = 0.0f;
            #pragma unroll
            for (int ni=0; ni<8; ni++){
                const int c0 = col_base + ni*8 + tg*2;
                float v0 = acc[mi][ni][2*h + 0] + W1b[c0]     + ph[c0];
                float v1 = acc[mi][ni][2*h + 1] + W1b[c0 + 1] + ph[c0 + 1];
                rsum += tanhf(v0) * Vw[c0] + tanhf(v1) * Vw[c0 + 1];
            }
            rsum += __shfl_xor_sync(0xffffffffu, rsum, 1);
            rsum += __shfl_xor_sync(0xffffffffu, rsum, 2);
            if (tg == 0) atomicAdd(&g_score[row], rsum);
        }
    }
}

// ---------------- kernel 3: softmax over T per batch ----------------
__global__ void softmax_kernel(float* __restrict__ w_out){   // w_out may be null
    const int b    = blockIdx.x;
    const int tid  = threadIdx.x;       // 576 threads = 18 full warps
    const int lane = tid & 31;
    const int wid  = tid >> 5;
    __shared__ float sred[32];

    const float s = g_score[b*Tt + tid];

    // max reduce
    float v = s;
    #pragma unroll
    for (int o=16;o>0;o>>=1) v = fmaxf(v, __shfl_xor_sync(0xffffffffu, v, o));
    if (lane == 0) sred[wid] = v;
    __syncthreads();
    if (tid < 32){
        float m = (tid < 18) ? sred[tid] : -3.4e38f;
        #pragma unroll
        for (int o=16;o>0;o>>=1) m = fmaxf(m, __shfl_xor_sync(0xffffffffu, m, o));
        sred[tid] = m;
    }
    __syncthreads();
    const float mx = sred[0];
    const float e  = expf(s - mx);
    __syncthreads();     // done reading sred before reuse

    // sum reduce
    float t = e;
    #pragma unroll
    for (int o=16;o>0;o>>=1) t += __shfl_xor_sync(0xffffffffu, t, o);
    if (lane == 0) sred[wid] = t;
    __syncthreads();
    if (tid < 32){
        float su = (tid < 18) ? sred[tid] : 0.0f;
        #pragma unroll
        for (int o=16;o>0;o>>=1) su += __shfl_xor_sync(0xffffffffu, su, o);
        sred[tid] = su;
    }
    __syncthreads();
    const float total = sred[0];

    const float wgt = e / total;
    g_weights[b*Tt + tid] = wgt;
    if (w_out) w_out[b*Tt + tid] = wgt;
}

// ---------------- kernel 4: context = sum_t w[b,t] * features[b,t,:] ----------------
__global__ void context_kernel(const float* __restrict__ feat,
                               float* __restrict__ ctx){
    const int b = blockIdx.y;
    const int d = blockIdx.x * blockDim.x + threadIdx.x;   // blockDim 256, gridDim.x 4
    __shared__ float sw[Tt];
    for (int t = threadIdx.x; t < Tt; t += blockDim.x) sw[t] = g_weights[b*Tt + t];
    __syncthreads();
    const float* fb = feat + (size_t)b*Tt*Dd + d;
    float acc = 0.0f;
    #pragma unroll 4
    for (int t = 0; t < Tt; ++t) acc += sw[t] * fb[(size_t)t*Dd];
    ctx[b*Dd + d] = acc;
}

// ---------------- launch ----------------
extern "C" void kernel_launch(void* const* d_in, const int* in_sizes, int n_in,
                              void* d_out, int out_size){
    const float* features = (const float*)d_in[0];
    const float* hidden   = (const float*)d_in[1];
    const float* W1w      = (const float*)d_in[2];
    const float* W1b      = (const float*)d_in[3];
    const float* W2w      = (const float*)d_in[4];
    const float* W2b      = (const float*)d_in[5];
    const float* Vw       = (const float*)d_in[6];
    // d_in[7] = V_b: softmax is shift-invariant, so it cannot affect either output.

    float* out = (float*)d_out;
    float* ctx_out = nullptr;
    float* w_out   = nullptr;
    if (out_size >= Bb*Dd + Mm)      { ctx_out = out; w_out = out + Bb*Dd; }
    else if (out_size == Bb*Dd)      { ctx_out = out; }
    else if (out_size == Mm)         { w_out = out; }
    else                             { ctx_out = out; }

    cudaFuncSetAttribute(gemm_score_kernel,
                         cudaFuncAttributeMaxDynamicSharedMemorySize,
                         GEMM_SMEM_BYTES);

    zero_score_kernel<<<Mm/256, 256>>>();
    projh_kernel<<<Bb, Uu>>>(hidden, W2w, W2b);

    dim3 gg(Uu/BN, Mm/BM);   // (4, 576)
    gemm_score_kernel<<<gg, 256, GEMM_SMEM_BYTES>>>(features, W1w, W1b, Vw);

    softmax_kernel<<<Bb, Tt>>>(w_out);

    if (ctx_out){
        dim3 gc(Dd/256, Bb); // (4, 128)
        context_kernel<<<gc, 256>>>(features, ctx_out);
    }
}

// round 5
// speedup vs baseline: 1.1867x; 1.1860x over previous
#include <cuda_runtime.h>
#include <cuda_fp16.h>
#include <math.h>
#include <stdint.h>

#define Bb 128
#define Tt 576
#define Dd 1024
#define Hh 1024
#define Uu 512
#define Mm (Bb*Tt)   // 73728

// ---------------- scratch (device globals; no allocs allowed) ----------------
__device__ float g_projh[Bb*Uu];     // hidden@W2 + W2_b + W1_b
__device__ float g_score[Mm];
__device__ float g_weights[Mm];

// ---------------- helpers ----------------
__device__ __forceinline__ uint32_t smem_u32(const void* p){
    uint32_t a;
    asm("{ .reg .u64 t; cvta.to.shared.u64 t, %1; cvt.u32.u64 %0, t; }" : "=r"(a) : "l"(p));
    return a;
}
// pack two fp32 -> f16x2 (x in low half = lower k index)
__device__ __forceinline__ uint32_t pack_h2(float x, float y){
    uint32_t u;
    asm("cvt.rn.f16x2.f32 %0, %1, %2;" : "=r"(u) : "f"(y), "f"(x));
    return u;
}
__device__ __forceinline__ float tanh_fast(float x){
    float y;
    asm("tanh.approx.f32 %0, %1;" : "=f"(y) : "f"(x));
    return y;
}
__device__ __forceinline__ void ldsm_x4(uint32_t* r, uint32_t addr){
    asm volatile("ldmatrix.sync.aligned.m8n8.x4.shared.b16 {%0,%1,%2,%3}, [%4];"
        : "=r"(r[0]), "=r"(r[1]), "=r"(r[2]), "=r"(r[3]) : "r"(addr));
}
__device__ __forceinline__ void ldsm_x4_t(uint32_t* r, uint32_t addr){
    asm volatile("ldmatrix.sync.aligned.m8n8.x4.trans.shared.b16 {%0,%1,%2,%3}, [%4];"
        : "=r"(r[0]), "=r"(r[1]), "=r"(r[2]), "=r"(r[3]) : "r"(addr));
}
__device__ __forceinline__ void mma_f16(float* c, const uint32_t* a, const uint32_t* b){
    asm volatile(
        "mma.sync.aligned.m16n8k16.row.col.f32.f16.f16.f32 "
        "{%0,%1,%2,%3}, {%4,%5,%6,%7}, {%8,%9}, {%0,%1,%2,%3};"
        : "+f"(c[0]), "+f"(c[1]), "+f"(c[2]), "+f"(c[3])
        : "r"(a[0]), "r"(a[1]), "r"(a[2]), "r"(a[3]), "r"(b[0]), "r"(b[1]));
}

// ---------------- kernel 0: zero the score accumulator ----------------
__global__ void zero_score_kernel(){
    int i = blockIdx.x * blockDim.x + threadIdx.x;
    if (i < Mm) g_score[i] = 0.0f;
}

// ---------------- kernel 1: proj_h = hidden @ W2 + W2_b + W1_b ----------------
__global__ void projh_kernel(const float* __restrict__ hidden,
                             const float* __restrict__ W2,
                             const float* __restrict__ W2b,
                             const float* __restrict__ W1b){
    __shared__ float sh[4*Hh];
    const int b0 = blockIdx.x * 4;       // grid = 32
    const int u  = threadIdx.x;          // 512 threads
    for (int i = threadIdx.x; i < 4*Hh; i += blockDim.x)
        sh[i] = hidden[(size_t)b0*Hh + i];
    __syncthreads();
    float a0 = 0.f, a1 = 0.f, a2 = 0.f, a3 = 0.f;
    #pragma unroll 4
    for (int h = 0; h < Hh; ++h){
        const float w = W2[(size_t)h*Uu + u];
        a0 += sh[h]*w; a1 += sh[Hh + h]*w; a2 += sh[2*Hh + h]*w; a3 += sh[3*Hh + h]*w;
    }
    const float bias = W1b[u] + W2b[u];
    g_projh[(size_t)(b0+0)*Uu + u] = a0 + bias;
    g_projh[(size_t)(b0+1)*Uu + u] = a1 + bias;
    g_projh[(size_t)(b0+2)*Uu + u] = a2 + bias;
    g_projh[(size_t)(b0+3)*Uu + u] = a3 + bias;
}

// ---------------- kernel 2: fp16 mma.sync GEMM + fused tanh·V epilogue ----------------
// score[m] += sum_n tanh( (A@W1)[m,n] + projh_bias[b(m),n] ) * Vw[n]
// CTA tile: BM=256 x BN=128, BK=32.  8 warps, each 64x64.
#define BM 256
#define BN 128
#define BK 32
#define SA_STR 40      // halves per A row (32 + 8 pad)  -> conflict-free ldmatrix
#define SB_STR 136     // halves per B row (128 + 8 pad) -> conflict-free ldmatrix.trans
#define SA_STAGE (BM*SA_STR*2)      // 20480 B
#define SB_STAGE (BK*SB_STR*2)      // 8704 B
#define GEMM_SMEM (2*SA_STAGE + 2*SB_STAGE)   // 58368 B
#define NKT (Dd/BK)    // 32

extern __shared__ char smem_raw[];

__global__ void __launch_bounds__(256)
gemm_score_kernel(const float* __restrict__ A,    // features [Mm, Dd]
                  const float* __restrict__ W1,   // [Dd, Uu]  (= [k][n], used directly)
                  const float* __restrict__ Vw)
{
    const uint32_t sbase = smem_u32(smem_raw);
    const int tid    = threadIdx.x;
    const int lane   = tid & 31;
    const int w      = tid >> 5;        // 8 warps
    const int warp_m = w >> 1;          // 0..3 : 64 rows each
    const int warp_n = w & 1;           // 0..1 : 64 cols each
    const int gid    = lane >> 2;
    const int tg     = lane & 3;
    const int m0     = blockIdx.y * BM; // gridDim.y = 288
    const int n0     = blockIdx.x * BN; // gridDim.x = 4

    uint32_t pah[16], pbh[8];           // prefetched, fp16-packed
    float acc[4][8][4];
    #pragma unroll
    for (int i=0;i<4;i++)
        #pragma unroll
        for (int j=0;j<8;j++)
            #pragma unroll
            for (int k=0;k<4;k++) acc[i][j][k] = 0.0f;

    // --- global->reg loads (converted to fp16 immediately) ---
    auto load_regs = [&](int kt){
        #pragma unroll
        for (int i=0;i<8;i++){                  // A: 2048 float4 slots
            int s = tid + i*256;
            int row = s >> 3, ch = s & 7;       // ch = 4-float chunk of k
            float4 v = *reinterpret_cast<const float4*>(
                &A[(size_t)(m0+row)*Dd + kt*BK + ch*4]);
            pah[2*i]   = pack_h2(v.x, v.y);
            pah[2*i+1] = pack_h2(v.z, v.w);
        }
        #pragma unroll
        for (int i=0;i<4;i++){                  // B: 1024 float4 slots
            int s = tid + i*256;
            int krow = s >> 5, ch = s & 31;     // ch = 4-float chunk of n
            float4 v = *reinterpret_cast<const float4*>(
                &W1[(size_t)(kt*BK+krow)*Uu + n0 + ch*4]);
            pbh[2*i]   = pack_h2(v.x, v.y);
            pbh[2*i+1] = pack_h2(v.z, v.w);
        }
    };
    auto store_stage = [&](int buf){
        char* dA = smem_raw + buf*SA_STAGE;
        char* dB = smem_raw + 2*SA_STAGE + buf*SB_STAGE;
        #pragma unroll
        for (int i=0;i<8;i++){
            int s = tid + i*256;
            int row = s >> 3, ch = s & 7;
            uint2 u; u.x = pah[2*i]; u.y = pah[2*i+1];
            *reinterpret_cast<uint2*>(dA + (row*SA_STR + ch*4)*2) = u;
        }
        #pragma unroll
        for (int i=0;i<4;i++){
            int s = tid + i*256;
            int krow = s >> 5, ch = s & 31;
            uint2 u; u.x = pbh[2*i]; u.y = pbh[2*i+1];
            *reinterpret_cast<uint2*>(dB + (krow*SB_STR + ch*4)*2) = u;
        }
    };
    auto compute = [&](int buf){
        const uint32_t sA = sbase + buf*SA_STAGE;
        const uint32_t sB = sbase + 2*SA_STAGE + buf*SB_STAGE;
        #pragma unroll
        for (int ks=0; ks<2; ks++){             // two k16 halves of BK=32
            uint32_t af[4][4], bf[8][2];
            #pragma unroll
            for (int mi=0;mi<4;mi++){
                uint32_t addr = sA + 2u*((warp_m*64 + mi*16 + (lane & 15))*SA_STR
                                          + ks*16 + (lane >> 4)*8);
                ldsm_x4(af[mi], addr);
            }
            #pragma unroll
            for (int np=0;np<4;np++){
                uint32_t r[4];
                uint32_t addr = sB + 2u*((ks*16 + (lane & 15))*SB_STR
                                          + warp_n*64 + np*16 + (lane >> 4)*8);
                ldsm_x4_t(r, addr);
                bf[2*np][0]   = r[0]; bf[2*np][1]   = r[1];
                bf[2*np+1][0] = r[2]; bf[2*np+1][1] = r[3];
            }
            #pragma unroll
            for (int mi=0;mi<4;mi++)
                #pragma unroll
                for (int ni=0;ni<8;ni++)
                    mma_f16(acc[mi][ni], af[mi], bf[ni]);
        }
    };

    load_regs(0);
    store_stage(0);
    __syncthreads();

    for (int kt = 0; kt < NKT; ++kt){
        const int cur = kt & 1;
        if (kt + 1 < NKT) load_regs(kt + 1);
        compute(cur);
        if (kt + 1 < NKT){
            store_stage(cur ^ 1);
            __syncthreads();
        }
    }

    // ----- epilogue: tanh + V contraction, quad-reduce, atomic accumulate -----
    const int nb = n0 + warp_n*64;
    #pragma unroll
    for (int mi=0; mi<4; mi++){
        #pragma unroll
        for (int h=0; h<2; h++){
            const int row = m0 + warp_m*64 + mi*16 + 8*h + gid;
            const int b   = row / Tt;
            const float* __restrict__ ph = g_projh + (size_t)b*Uu;   // has both biases
            float rsum = 0.0f;
            #pragma unroll
            for (int ni=0; ni<8; ni++){
                const int c0 = nb + ni*8 + tg*2;
                const float v0 = acc[mi][ni][2*h + 0] + ph[c0];
                const float v1 = acc[mi][ni][2*h + 1] + ph[c0 + 1];
                rsum += tanh_fast(v0) * Vw[c0] + tanh_fast(v1) * Vw[c0 + 1];
            }
            rsum += __shfl_xor_sync(0xffffffffu, rsum, 1);
            rsum += __shfl_xor_sync(0xffffffffu, rsum, 2);
            if (tg == 0) atomicAdd(&g_score[row], rsum);
        }
    }
}

// ---------------- kernel 3: softmax over T per batch ----------------
__global__ void softmax_kernel(float* __restrict__ w_out){
    const int b    = blockIdx.x;
    const int tid  = threadIdx.x;       // 576 threads
    const int lane = tid & 31;
    const int wid  = tid >> 5;
    __shared__ float sred[32];

    const float s = g_score[b*Tt + tid];

    float v = s;
    #pragma unroll
    for (int o=16;o>0;o>>=1) v = fmaxf(v, __shfl_xor_sync(0xffffffffu, v, o));
    if (lane == 0) sred[wid] = v;
    __syncthreads();
    if (tid < 32){
        float m = (tid < 18) ? sred[tid] : -3.4e38f;
        #pragma unroll
        for (int o=16;o>0;o>>=1) m = fmaxf(m, __shfl_xor_sync(0xffffffffu, m, o));
        sred[tid] = m;
    }
    __syncthreads();
    const float mx = sred[0];
    const float e  = expf(s - mx);
    __syncthreads();

    float t = e;
    #pragma unroll
    for (int o=16;o>0;o>>=1) t += __shfl_xor_sync(0xffffffffu, t, o);
    if (lane == 0) sred[wid] = t;
    __syncthreads();
    if (tid < 32){
        float su = (tid < 18) ? sred[tid] : 0.0f;
        #pragma unroll
        for (int o=16;o>0;o>>=1) su += __shfl_xor_sync(0xffffffffu, su, o);
        sred[tid] = su;
    }
    __syncthreads();
    const float total = sred[0];

    const float wgt = e / total;
    g_weights[b*Tt + tid] = wgt;
    if (w_out) w_out[b*Tt + tid] = wgt;
}

// ---------------- kernel 4: context = sum_t w[b,t] * features[b,t,:] ----------------
__global__ void context_kernel(const float* __restrict__ feat,
                               float* __restrict__ ctx){
    const int b = blockIdx.y;
    const int d = blockIdx.x * blockDim.x + threadIdx.x;
    __shared__ float sw[Tt];
    for (int t = threadIdx.x; t < Tt; t += blockDim.x) sw[t] = g_weights[b*Tt + t];
    __syncthreads();
    const float* fb = feat + (size_t)b*Tt*Dd + d;
    float acc = 0.0f;
    #pragma unroll 4
    for (int t = 0; t < Tt; ++t) acc += sw[t] * fb[(size_t)t*Dd];
    ctx[b*Dd + d] = acc;
}

// ---------------- launch ----------------
extern "C" void kernel_launch(void* const* d_in, const int* in_sizes, int n_in,
                              void* d_out, int out_size){
    const float* features = (const float*)d_in[0];
    const float* hidden   = (const float*)d_in[1];
    const float* W1w      = (const float*)d_in[2];
    const float* W1b      = (const float*)d_in[3];
    const float* W2w      = (const float*)d_in[4];
    const float* W2b      = (const float*)d_in[5];
    const float* Vw       = (const float*)d_in[6];
    // d_in[7] = V_b: softmax is shift-invariant -> cannot affect outputs.

    float* out = (float*)d_out;
    float* ctx_out = nullptr;
    float* w_out   = nullptr;
    if (out_size >= Bb*Dd + Mm)      { ctx_out = out; w_out = out + Bb*Dd; }
    else if (out_size == Bb*Dd)      { ctx_out = out; }
    else if (out_size == Mm)         { w_out = out; }
    else                             { ctx_out = out; }

    cudaFuncSetAttribute(gemm_score_kernel,
                         cudaFuncAttributeMaxDynamicSharedMemorySize, GEMM_SMEM);

    zero_score_kernel<<<Mm/256, 256>>>();
    projh_kernel<<<Bb/4, Uu>>>(hidden, W2w, W2b, W1b);

    dim3 gg(Uu/BN, Mm/BM);   // (4, 288)
    gemm_score_kernel<<<gg, 256, GEMM_SMEM>>>(features, W1w, Vw);

    softmax_kernel<<<Bb, Tt>>>(w_out);

    if (ctx_out){
        dim3 gc(Dd/256, Bb); // (4, 128)
        context_kernel<<<gc, 256>>>(features, ctx_out);
    }
}